// round 3
// baseline (speedup 1.0000x reference)
#include <cuda_runtime.h>

// Problem dims
#define Nb  8
#define Ssz 1024
#define Esz 1024
#define Hn  16
#define DKs 64
#define NSE (Nb*Ssz*Esz)                 // 8388608
#define NHSS (134217728)                 // Nb*Hn*Ssz*Ssz

// Scratch (static device globals; allocation at module load is allowed)
__device__ float g_Q[NSE];
__device__ float g_K[NSE];
__device__ float g_V[NSE];
__device__ float g_O[NSE];
__device__ float g_attn_fb[NHSS];        // only used if harness output excludes attn_weights

// ---------------------------------------------------------------------------
// Generic C[M,1024] = A[M,1024] @ W[1024,1024] + bias, tiled 128x128x16.
// grid: (1024/128, M/128), block 256 threads, 8x8 register tile per thread.
// ---------------------------------------------------------------------------
__global__ __launch_bounds__(256) void gemm_bias_kernel(
    const float* __restrict__ A, const float* __restrict__ W,
    const float* __restrict__ bias, float* __restrict__ C) {
  __shared__ float As[16][129];   // [k][m], padded pitch -> conflict-free
  __shared__ float Ws[16][128];   // [k][n]
  const int tid = threadIdx.x;
  const int tx = tid & 15, ty = tid >> 4;
  const int m0 = blockIdx.y * 128, n0 = blockIdx.x * 128;
  float acc[8][8] = {};
  for (int kt = 0; kt < 1024; kt += 16) {
#pragma unroll
    for (int j = 0; j < 2; j++) {
      int e = tid + 256 * j;
      int m = e >> 2, k4 = (e & 3) * 4;
      float4 v = *(const float4*)&A[(size_t)(m0 + m) * 1024 + kt + k4];
      As[k4 + 0][m] = v.x; As[k4 + 1][m] = v.y;
      As[k4 + 2][m] = v.z; As[k4 + 3][m] = v.w;
    }
#pragma unroll
    for (int j = 0; j < 2; j++) {
      int e = tid + 256 * j;
      int k = e >> 5, nf = (e & 31) * 4;
      *(float4*)&Ws[k][nf] = *(const float4*)&W[(size_t)(kt + k) * 1024 + n0 + nf];
    }
    __syncthreads();
#pragma unroll
    for (int kk = 0; kk < 16; kk++) {
      float a[8], w[8];
#pragma unroll
      for (int i = 0; i < 8; i++) a[i] = As[kk][ty * 8 + i];
#pragma unroll
      for (int j = 0; j < 8; j++) w[j] = Ws[kk][tx * 8 + j];
#pragma unroll
      for (int i = 0; i < 8; i++)
#pragma unroll
        for (int j = 0; j < 8; j++) acc[i][j] = fmaf(a[i], w[j], acc[i][j]);
    }
    __syncthreads();
  }
#pragma unroll
  for (int i = 0; i < 8; i++) {
    int m = m0 + ty * 8 + i;
#pragma unroll
    for (int j4 = 0; j4 < 2; j4++) {
      int n = n0 + tx * 8 + j4 * 4;
      float4 v;
      v.x = acc[i][j4 * 4 + 0] + bias[n + 0];
      v.y = acc[i][j4 * 4 + 1] + bias[n + 1];
      v.z = acc[i][j4 * 4 + 2] + bias[n + 2];
      v.w = acc[i][j4 * 4 + 3] + bias[n + 3];
      *(float4*)&C[(size_t)m * 1024 + n] = v;
    }
  }
}

// ---------------------------------------------------------------------------
// logits[n,h,s,t] = (Qh . Kh)/8, masked to -1e9. Written into attn buffer.
// mask is int32 (bool promoted by harness): nonzero -> masked.
// grid: (S/128 t-tiles, S/128 m-tiles, N*H), block 256.
// ---------------------------------------------------------------------------
__global__ __launch_bounds__(256) void qk_kernel(
    const int* __restrict__ mask, float* __restrict__ attn) {
  __shared__ float Qs[16][129];
  __shared__ float Ks[16][129];
  const int tid = threadIdx.x;
  const int tx = tid & 15, ty = tid >> 4;
  const int t0 = blockIdx.x * 128, m0 = blockIdx.y * 128;
  const int nh = blockIdx.z, n = nh >> 4, h = nh & 15;
  const float* Qb = g_Q + (size_t)n * Ssz * Esz + h * DKs;
  const float* Kb = g_K + (size_t)n * Ssz * Esz + h * DKs;
  float acc[8][8] = {};
  for (int kt = 0; kt < 64; kt += 16) {
#pragma unroll
    for (int j = 0; j < 2; j++) {
      int e = tid + 256 * j;
      int m = e >> 2, k4 = (e & 3) * 4;
      float4 v = *(const float4*)&Qb[(size_t)(m0 + m) * 1024 + kt + k4];
      Qs[k4 + 0][m] = v.x; Qs[k4 + 1][m] = v.y;
      Qs[k4 + 2][m] = v.z; Qs[k4 + 3][m] = v.w;
      float4 u = *(const float4*)&Kb[(size_t)(t0 + m) * 1024 + kt + k4];
      Ks[k4 + 0][m] = u.x; Ks[k4 + 1][m] = u.y;
      Ks[k4 + 2][m] = u.z; Ks[k4 + 3][m] = u.w;
    }
    __syncthreads();
#pragma unroll
    for (int kk = 0; kk < 16; kk++) {
      float a[8], w[8];
#pragma unroll
      for (int i = 0; i < 8; i++) a[i] = Qs[kk][ty * 8 + i];
#pragma unroll
      for (int j = 0; j < 8; j++) w[j] = Ks[kk][tx * 8 + j];
#pragma unroll
      for (int i = 0; i < 8; i++)
#pragma unroll
        for (int j = 0; j < 8; j++) acc[i][j] = fmaf(a[i], w[j], acc[i][j]);
    }
    __syncthreads();
  }
#pragma unroll
  for (int i = 0; i < 8; i++) {
    int row = m0 + ty * 8 + i;
    const int* mrow = mask + (size_t)(n * Ssz + row) * Ssz + t0 + tx * 8;
    int4 ma = *(const int4*)mrow;
    int4 mb = *(const int4*)(mrow + 4);
    int mv[8] = {ma.x, ma.y, ma.z, ma.w, mb.x, mb.y, mb.z, mb.w};
    float* arow = attn + ((size_t)nh * Ssz + row) * Ssz + t0 + tx * 8;
#pragma unroll
    for (int j = 0; j < 8; j++) {
      float vv = acc[i][j] * 0.125f;
      if (mv[j] != 0) vv = -1e9f;
      arow[j] = vv;
    }
  }
}

// ---------------------------------------------------------------------------
// In-place row softmax over rows of length 1024. grid: (1024 rows, N*H).
// ---------------------------------------------------------------------------
__global__ __launch_bounds__(256) void softmax_kernel(float* __restrict__ attn) {
  __shared__ float red[8];
  const int tid = threadIdx.x;
  size_t rowIdx = (size_t)blockIdx.y * 1024 + blockIdx.x;
  float* row = attn + rowIdx * 1024;
  float4 v = ((float4*)row)[tid];
  float m = fmaxf(fmaxf(v.x, v.y), fmaxf(v.z, v.w));
#pragma unroll
  for (int o = 16; o > 0; o >>= 1) m = fmaxf(m, __shfl_xor_sync(0xffffffffu, m, o));
  if ((tid & 31) == 0) red[tid >> 5] = m;
  __syncthreads();
  m = fmaxf(fmaxf(fmaxf(red[0], red[1]), fmaxf(red[2], red[3])),
            fmaxf(fmaxf(red[4], red[5]), fmaxf(red[6], red[7])));
  float4 e;
  e.x = __expf(v.x - m); e.y = __expf(v.y - m);
  e.z = __expf(v.z - m); e.w = __expf(v.w - m);
  float s = (e.x + e.y) + (e.z + e.w);
#pragma unroll
  for (int o = 16; o > 0; o >>= 1) s += __shfl_xor_sync(0xffffffffu, s, o);
  __syncthreads();
  if ((tid & 31) == 0) red[tid >> 5] = s;
  __syncthreads();
  s = ((red[0] + red[1]) + (red[2] + red[3])) + ((red[4] + red[5]) + (red[6] + red[7]));
  float inv = 1.0f / s;
  e.x *= inv; e.y *= inv; e.z *= inv; e.w *= inv;
  ((float4*)row)[tid] = e;
}

// ---------------------------------------------------------------------------
// O[n,s,h*64+d] = sum_t P[n,h,s,t] * V[n,t,h*64+d]. grid: (S/128, N*H).
// ---------------------------------------------------------------------------
__global__ __launch_bounds__(256) void pv_kernel(const float* __restrict__ attn) {
  __shared__ float Ps[16][129];
  __shared__ float Vs[16][64];
  const int tid = threadIdx.x;
  const int tx = tid & 15, ty = tid >> 4;
  const int mb = blockIdx.x * 128;
  const int nh = blockIdx.y, n = nh >> 4, h = nh & 15;
  const float* P = attn + (size_t)nh * Ssz * Ssz;
  const float* Vb = g_V + (size_t)n * Ssz * Esz + h * DKs;
  float acc[8][4] = {};
  for (int kt = 0; kt < 1024; kt += 16) {
#pragma unroll
    for (int j = 0; j < 2; j++) {
      int e = tid + 256 * j;
      int m = e >> 2, k4 = (e & 3) * 4;
      float4 v = *(const float4*)&P[(size_t)(mb + m) * 1024 + kt + k4];
      Ps[k4 + 0][m] = v.x; Ps[k4 + 1][m] = v.y;
      Ps[k4 + 2][m] = v.z; Ps[k4 + 3][m] = v.w;
    }
    {
      int k = tid >> 4, df = (tid & 15) * 4;
      *(float4*)&Vs[k][df] = *(const float4*)&Vb[(size_t)(kt + k) * 1024 + df];
    }
    __syncthreads();
#pragma unroll
    for (int kk = 0; kk < 16; kk++) {
      float a[8], w[4];
#pragma unroll
      for (int i = 0; i < 8; i++) a[i] = Ps[kk][ty * 8 + i];
#pragma unroll
      for (int j = 0; j < 4; j++) w[j] = Vs[kk][tx * 4 + j];
#pragma unroll
      for (int i = 0; i < 8; i++)
#pragma unroll
        for (int j = 0; j < 4; j++) acc[i][j] = fmaf(a[i], w[j], acc[i][j]);
    }
    __syncthreads();
  }
  float* Ob = g_O + (size_t)n * Ssz * Esz + h * DKs;
#pragma unroll
  for (int i = 0; i < 8; i++) {
    float4 v;
    v.x = acc[i][0]; v.y = acc[i][1]; v.z = acc[i][2]; v.w = acc[i][3];
    *(float4*)&Ob[(size_t)(mb + ty * 8 + i) * 1024 + tx * 4] = v;
  }
}

// ---------------------------------------------------------------------------
extern "C" void kernel_launch(void* const* d_in, const int* in_sizes, int n_in,
                              void* d_out, int out_size) {
  const float* q  = (const float*)d_in[0];
  const float* k  = (const float*)d_in[1];
  const float* v  = (const float*)d_in[2];
  const int*   mask = (const int*)d_in[3];   // bool promoted to int32 by harness
  const float* wq = (const float*)d_in[4];
  const float* bq = (const float*)d_in[5];
  const float* wk = (const float*)d_in[6];
  const float* bk = (const float*)d_in[7];
  const float* wv = (const float*)d_in[8];
  const float* bv = (const float*)d_in[9];
  const float* wo = (const float*)d_in[10];
  const float* bo = (const float*)d_in[11];
  float* out = (float*)d_out;

  float *Qp, *Kp, *Vp, *Op, *attn;
  cudaGetSymbolAddress((void**)&Qp, g_Q);
  cudaGetSymbolAddress((void**)&Kp, g_K);
  cudaGetSymbolAddress((void**)&Vp, g_V);
  cudaGetSymbolAddress((void**)&Op, g_O);
  if ((long long)out_size >= (long long)NSE + (long long)NHSS) {
    attn = out + NSE;                     // attn_weights live in d_out
  } else {
    cudaGetSymbolAddress((void**)&attn, g_attn_fb);
  }

  dim3 gp(8, 64);  // 1024/128 x 8192/128
  gemm_bias_kernel<<<gp, 256>>>(q, wq, bq, Qp);
  gemm_bias_kernel<<<gp, 256>>>(k, wk, bk, Kp);
  gemm_bias_kernel<<<gp, 256>>>(v, wv, bv, Vp);
  qk_kernel<<<dim3(8, 8, 128), 256>>>(mask, attn);
  softmax_kernel<<<dim3(1024, 128), 256>>>(attn);
  pv_kernel<<<dim3(8, 128), 256>>>(attn);
  gemm_bias_kernel<<<gp, 256>>>(Op, wo, bo, out);
}

// round 4
// speedup vs baseline: 1.4709x; 1.4709x over previous
#include <cuda_runtime.h>
#include <cuda_bf16.h>

// Problem dims
#define Nb  8
#define Ssz 1024
#define Esz 1024
#define Hn  16
#define DKs 64
#define NSE (Nb*Ssz*Esz)                 // 8388608
#define NHSS (134217728)                 // Nb*Hn*Ssz*Ssz

// Scratch
__device__ float g_Q[NSE];
__device__ float g_K[NSE];
__device__ float g_Vt[NSE];              // [nh][d][t] transposed V
__device__ float g_O[NSE];
__device__ float g_Wt[4 * Esz * Esz];    // transposed weights
__device__ float g_attn_fb[NHSS];        // fallback if attn not in d_out

// ---------------------------------------------------------------------------
// bf16 split helpers: a = hi + lo (each bf16), 3-term mma product.
// ---------------------------------------------------------------------------
__device__ __forceinline__ void split4(float4 v, unsigned& h01, unsigned& h23,
                                       unsigned& l01, unsigned& l23) {
  __nv_bfloat162 h0 = __float22bfloat162_rn(make_float2(v.x, v.y));
  __nv_bfloat162 h1 = __float22bfloat162_rn(make_float2(v.z, v.w));
  float2 f0 = __bfloat1622float2(h0);
  float2 f1 = __bfloat1622float2(h1);
  __nv_bfloat162 l0 = __float22bfloat162_rn(make_float2(v.x - f0.x, v.y - f0.y));
  __nv_bfloat162 l1 = __float22bfloat162_rn(make_float2(v.z - f1.x, v.w - f1.y));
  h01 = *reinterpret_cast<unsigned*>(&h0);
  h23 = *reinterpret_cast<unsigned*>(&h1);
  l01 = *reinterpret_cast<unsigned*>(&l0);
  l23 = *reinterpret_cast<unsigned*>(&l1);
}

__device__ __forceinline__ void mma4(float* c, const unsigned* a, unsigned b0, unsigned b1) {
  asm volatile(
      "mma.sync.aligned.m16n8k16.row.col.f32.bf16.bf16.f32 "
      "{%0,%1,%2,%3}, {%4,%5,%6,%7}, {%8,%9}, {%0,%1,%2,%3};\n"
      : "+f"(c[0]), "+f"(c[1]), "+f"(c[2]), "+f"(c[3])
      : "r"(a[0]), "r"(a[1]), "r"(a[2]), "r"(a[3]), "r"(b0), "r"(b1));
}

// ---------------------------------------------------------------------------
// Load OUTER x 32(k) fp32 tile -> packed bf16 hi/lo smem [outer][kp], pitch 20.
// Word kp holds bf16 pair (k=2kp, k=2kp+1).
// ---------------------------------------------------------------------------
template <int OUTER>
__device__ __forceinline__ void load_tile(const float* __restrict__ g, int ld,
                                          unsigned* sh, unsigned* sl, int tid) {
#pragma unroll
  for (int j = 0; j < OUTER / 32; j++) {
    int e = tid + 256 * j;
    int m = e >> 3, kq = e & 7;
    float4 v = *(const float4*)(g + (size_t)m * ld + 4 * kq);
    unsigned h01, h23, l01, l23;
    split4(v, h01, h23, l01, l23);
    int base = m * 20 + 2 * kq;
    sh[base] = h01; sh[base + 1] = h23;
    sl[base] = l01; sl[base + 1] = l23;
  }
}

// ---------------------------------------------------------------------------
// Warp-tile compute over one 32-k smem tile (2 chunks of k16), 3-term split.
// A warp tile: MT m16-tiles x NT n8-tiles at (wm0, wn0).
// ---------------------------------------------------------------------------
template <int MT, int NT>
__device__ __forceinline__ void compute_tile(
    const unsigned* Ah, const unsigned* Al, const unsigned* Bh, const unsigned* Bl,
    int wm0, int wn0, int gr, int q, float (&acc)[MT][NT][4]) {
#pragma unroll
  for (int c = 0; c < 2; c++) {
    unsigned ah[MT][4], al[MT][4];
#pragma unroll
    for (int mt = 0; mt < MT; mt++) {
      int r0 = (wm0 + 16 * mt + gr) * 20 + 8 * c + q;
      int r1 = (wm0 + 16 * mt + 8 + gr) * 20 + 8 * c + q;
      ah[mt][0] = Ah[r0]; ah[mt][1] = Ah[r1];
      ah[mt][2] = Ah[r0 + 4]; ah[mt][3] = Ah[r1 + 4];
      al[mt][0] = Al[r0]; al[mt][1] = Al[r1];
      al[mt][2] = Al[r0 + 4]; al[mt][3] = Al[r1 + 4];
    }
#pragma unroll
    for (int nt = 0; nt < NT; nt++) {
      int rb = (wn0 + 8 * nt + gr) * 20 + 8 * c + q;
      unsigned bh0 = Bh[rb], bh1 = Bh[rb + 4];
      unsigned bl0 = Bl[rb], bl1 = Bl[rb + 4];
#pragma unroll
      for (int mt = 0; mt < MT; mt++) {
        mma4(acc[mt][nt], ah[mt], bh0, bh1);
        mma4(acc[mt][nt], ah[mt], bl0, bl1);
        mma4(acc[mt][nt], al[mt], bh0, bh1);
      }
    }
  }
}

// ---------------------------------------------------------------------------
// 1024x1024 transpose: Wt[n][k] = W[k][n]
// ---------------------------------------------------------------------------
__global__ void transpose1024(const float* __restrict__ W, float* __restrict__ Wt) {
  __shared__ float tile[32][33];
  int bx = blockIdx.x * 32, by = blockIdx.y * 32;
  int x = threadIdx.x, y0 = threadIdx.y;
#pragma unroll
  for (int i = 0; i < 32; i += 8)
    tile[y0 + i][x] = W[(size_t)(by + y0 + i) * 1024 + bx + x];
  __syncthreads();
#pragma unroll
  for (int i = 0; i < 32; i += 8)
    Wt[(size_t)(bx + y0 + i) * 1024 + by + x] = tile[x][y0 + i];
}

// ---------------------------------------------------------------------------
// Projection GEMM: C[m][n] = A[m][:] . Wt[n][:] + bias[n]
// CTA 128x128, warps 2m x 4n (warp tile 64x32). VT: write V transposed layout.
// ---------------------------------------------------------------------------
template <bool VT>
__global__ __launch_bounds__(256, 2) void proj_mma(
    const float* __restrict__ A, const float* __restrict__ Wt,
    const float* __restrict__ bias, float* __restrict__ C) {
  __shared__ unsigned Ah[2560], Al[2560], Bh[2560], Bl[2560];
  const int tid = threadIdx.x;
  const int wid = tid >> 5, lane = tid & 31;
  const int gr = lane >> 2, q = lane & 3;
  const int wm0 = (wid >> 2) * 64, wn0 = (wid & 3) * 32;
  const int m0 = blockIdx.y * 128, n0 = blockIdx.x * 128;
  float acc[4][4][4] = {};
  for (int kt = 0; kt < 1024; kt += 32) {
    load_tile<128>(A + (size_t)m0 * 1024 + kt, 1024, Ah, Al, tid);
    load_tile<128>(Wt + (size_t)n0 * 1024 + kt, 1024, Bh, Bl, tid);
    __syncthreads();
    compute_tile<4, 4>(Ah, Al, Bh, Bl, wm0, wn0, gr, q, acc);
    __syncthreads();
  }
#pragma unroll
  for (int mt = 0; mt < 4; mt++) {
#pragma unroll
    for (int nt = 0; nt < 4; nt++) {
      int row = m0 + wm0 + 16 * mt + gr;
      int col = n0 + wn0 + 8 * nt + 2 * q;
      float b0 = bias[col], b1 = bias[col + 1];
      if (!VT) {
        float2 v0 = {acc[mt][nt][0] + b0, acc[mt][nt][1] + b1};
        float2 v1 = {acc[mt][nt][2] + b0, acc[mt][nt][3] + b1};
        *(float2*)&C[(size_t)row * 1024 + col] = v0;
        *(float2*)&C[(size_t)(row + 8) * 1024 + col] = v1;
      } else {
        int nb = row >> 10, s = row & 1023;
        int h = col >> 6, d = col & 63;
        float* p = C + (((size_t)(nb * 16 + h)) * 64 + d) * 1024 + s;
        p[0] = acc[mt][nt][0] + b0;
        p[1024] = acc[mt][nt][1] + b1;
        p[8] = acc[mt][nt][2] + b0;
        p[1024 + 8] = acc[mt][nt][3] + b1;
      }
    }
  }
}

// ---------------------------------------------------------------------------
// QK^T: logits = (Qh.Kh)/8, masked -> attn buffer. CTA 128(m) x 128(t), K=64.
// ---------------------------------------------------------------------------
__global__ __launch_bounds__(256, 2) void qk_mma(
    const int* __restrict__ mask, float* __restrict__ attn) {
  __shared__ unsigned Ah[2560], Al[2560], Bh[2560], Bl[2560];
  const int tid = threadIdx.x;
  const int wid = tid >> 5, lane = tid & 31;
  const int gr = lane >> 2, q = lane & 3;
  const int wm0 = (wid >> 2) * 64, wn0 = (wid & 3) * 32;
  const int t0 = blockIdx.x * 128, m0 = blockIdx.y * 128;
  const int nh = blockIdx.z, nb = nh >> 4, h = nh & 15;
  const float* Qb = g_Q + (size_t)(nb * 1024 + m0) * 1024 + h * 64;
  const float* Kb = g_K + (size_t)(nb * 1024 + t0) * 1024 + h * 64;
  float acc[4][4][4] = {};
  for (int kt = 0; kt < 64; kt += 32) {
    load_tile<128>(Qb + kt, 1024, Ah, Al, tid);
    load_tile<128>(Kb + kt, 1024, Bh, Bl, tid);
    __syncthreads();
    compute_tile<4, 4>(Ah, Al, Bh, Bl, wm0, wn0, gr, q, acc);
    __syncthreads();
  }
#pragma unroll
  for (int mt = 0; mt < 4; mt++) {
#pragma unroll
    for (int nt = 0; nt < 4; nt++) {
      int row = m0 + wm0 + 16 * mt + gr;
      int t = t0 + wn0 + 8 * nt + 2 * q;
      int2 mA = *(const int2*)&mask[(size_t)(nb * 1024 + row) * 1024 + t];
      int2 mB = *(const int2*)&mask[(size_t)(nb * 1024 + row + 8) * 1024 + t];
      float2 v0, v1;
      v0.x = mA.x ? -1e9f : acc[mt][nt][0] * 0.125f;
      v0.y = mA.y ? -1e9f : acc[mt][nt][1] * 0.125f;
      v1.x = mB.x ? -1e9f : acc[mt][nt][2] * 0.125f;
      v1.y = mB.y ? -1e9f : acc[mt][nt][3] * 0.125f;
      *(float2*)&attn[((size_t)nh * 1024 + row) * 1024 + t] = v0;
      *(float2*)&attn[((size_t)nh * 1024 + row + 8) * 1024 + t] = v1;
    }
  }
}

// ---------------------------------------------------------------------------
// In-place row softmax over rows of length 1024. grid: (1024 rows, N*H).
// ---------------------------------------------------------------------------
__global__ __launch_bounds__(256) void softmax_kernel(float* __restrict__ attn) {
  __shared__ float red[8];
  const int tid = threadIdx.x;
  size_t rowIdx = (size_t)blockIdx.y * 1024 + blockIdx.x;
  float* row = attn + rowIdx * 1024;
  float4 v = ((float4*)row)[tid];
  float m = fmaxf(fmaxf(v.x, v.y), fmaxf(v.z, v.w));
#pragma unroll
  for (int o = 16; o > 0; o >>= 1) m = fmaxf(m, __shfl_xor_sync(0xffffffffu, m, o));
  if ((tid & 31) == 0) red[tid >> 5] = m;
  __syncthreads();
  m = fmaxf(fmaxf(fmaxf(red[0], red[1]), fmaxf(red[2], red[3])),
            fmaxf(fmaxf(red[4], red[5]), fmaxf(red[6], red[7])));
  float4 e;
  e.x = __expf(v.x - m); e.y = __expf(v.y - m);
  e.z = __expf(v.z - m); e.w = __expf(v.w - m);
  float s = (e.x + e.y) + (e.z + e.w);
#pragma unroll
  for (int o = 16; o > 0; o >>= 1) s += __shfl_xor_sync(0xffffffffu, s, o);
  __syncthreads();
  if ((tid & 31) == 0) red[tid >> 5] = s;
  __syncthreads();
  s = ((red[0] + red[1]) + (red[2] + red[3])) + ((red[4] + red[5]) + (red[6] + red[7]));
  float inv = 1.0f / s;
  e.x *= inv; e.y *= inv; e.z *= inv; e.w *= inv;
  ((float4*)row)[tid] = e;
}

// ---------------------------------------------------------------------------
// PV: O[s][h*64+d] = sum_t P[s][t] * Vt[nh][d][t]. CTA 128(m) x 64(d), K=1024.
// warps 2m x 4n (warp tile 64x16): MT=4, NT=2.
// ---------------------------------------------------------------------------
__global__ __launch_bounds__(256, 2) void pv_mma(const float* __restrict__ attn) {
  __shared__ unsigned Ah[2560], Al[2560], Bh[1280], Bl[1280];
  const int tid = threadIdx.x;
  const int wid = tid >> 5, lane = tid & 31;
  const int gr = lane >> 2, q = lane & 3;
  const int wm0 = (wid >> 2) * 64, wn0 = (wid & 3) * 16;
  const int m0 = blockIdx.x * 128;
  const int nh = blockIdx.y, nb = nh >> 4, h = nh & 15;
  const float* P = attn + (size_t)nh * 1024 * 1024 + (size_t)m0 * 1024;
  const float* Vb = g_Vt + (size_t)nh * 64 * 1024;
  float acc[4][2][4] = {};
  for (int kt = 0; kt < 1024; kt += 32) {
    load_tile<128>(P + kt, 1024, Ah, Al, tid);
    load_tile<64>(Vb + kt, 1024, Bh, Bl, tid);
    __syncthreads();
    compute_tile<4, 2>(Ah, Al, Bh, Bl, wm0, wn0, gr, q, acc);
    __syncthreads();
  }
#pragma unroll
  for (int mt = 0; mt < 4; mt++) {
#pragma unroll
    for (int nt = 0; nt < 2; nt++) {
      int s = m0 + wm0 + 16 * mt + gr;
      int e = h * 64 + wn0 + 8 * nt + 2 * q;
      float2 v0 = {acc[mt][nt][0], acc[mt][nt][1]};
      float2 v1 = {acc[mt][nt][2], acc[mt][nt][3]};
      *(float2*)&g_O[(size_t)(nb * 1024 + s) * 1024 + e] = v0;
      *(float2*)&g_O[(size_t)(nb * 1024 + s + 8) * 1024 + e] = v1;
    }
  }
}

// ---------------------------------------------------------------------------
extern "C" void kernel_launch(void* const* d_in, const int* in_sizes, int n_in,
                              void* d_out, int out_size) {
  const float* q  = (const float*)d_in[0];
  const float* k  = (const float*)d_in[1];
  const float* v  = (const float*)d_in[2];
  const int*   mask = (const int*)d_in[3];
  const float* wq = (const float*)d_in[4];
  const float* bq = (const float*)d_in[5];
  const float* wk = (const float*)d_in[6];
  const float* bk = (const float*)d_in[7];
  const float* wv = (const float*)d_in[8];
  const float* bv = (const float*)d_in[9];
  const float* wo = (const float*)d_in[10];
  const float* bo = (const float*)d_in[11];
  float* out = (float*)d_out;

  float *Qp, *Kp, *Vtp, *Op, *Wtp, *attn;
  cudaGetSymbolAddress((void**)&Qp, g_Q);
  cudaGetSymbolAddress((void**)&Kp, g_K);
  cudaGetSymbolAddress((void**)&Vtp, g_Vt);
  cudaGetSymbolAddress((void**)&Op, g_O);
  cudaGetSymbolAddress((void**)&Wtp, g_Wt);
  if ((long long)out_size >= (long long)NSE + (long long)NHSS) {
    attn = out + NSE;
  } else {
    cudaGetSymbolAddress((void**)&attn, g_attn_fb);
  }
  float* Wtq = Wtp;
  float* Wtk = Wtp + 1 * Esz * Esz;
  float* Wtv = Wtp + 2 * Esz * Esz;
  float* Wto = Wtp + 3 * Esz * Esz;

  dim3 tb(32, 8), tg(32, 32);
  transpose1024<<<tg, tb>>>(wq, Wtq);
  transpose1024<<<tg, tb>>>(wk, Wtk);
  transpose1024<<<tg, tb>>>(wv, Wtv);
  transpose1024<<<tg, tb>>>(wo, Wto);

  dim3 gp(8, 64);
  proj_mma<false><<<gp, 256>>>(q, Wtq, bq, Qp);
  proj_mma<false><<<gp, 256>>>(k, Wtk, bk, Kp);
  proj_mma<true><<<gp, 256>>>(v, Wtv, bv, Vtp);
  qk_mma<<<dim3(8, 8, 128), 256>>>(mask, attn);
  softmax_kernel<<<dim3(1024, 128), 256>>>(attn);
  pv_mma<<<dim3(8, 128), 256>>>(attn);
  proj_mma<false><<<gp, 256>>>(Op, Wto, bo, out);
}

// round 5
// speedup vs baseline: 2.1666x; 1.4729x over previous
#include <cuda_runtime.h>
#include <cuda_bf16.h>

#define Nb  8
#define Ssz 1024
#define Esz 1024
#define Hn  16
#define DKs 64
#define NSE (Nb*Ssz*Esz)                 // 8388608
#define NSE2 (NSE/2)
#define EE2 (Esz*Esz/2)
#define NHSS (134217728)

// Packed bf16 hi/lo planes (word i = pair (2i, 2i+1) along k)
__device__ unsigned g_Inh[NSE2], g_Inl[NSE2];      // current projection input
__device__ unsigned g_Qh[NSE2], g_Ql[NSE2];
__device__ unsigned g_Kh[NSE2], g_Kl[NSE2];
__device__ unsigned g_Vth[NSE2], g_Vtl[NSE2];      // [nh][d][t/2]
__device__ unsigned g_Oh[NSE2], g_Ol[NSE2];
__device__ unsigned g_Wth[4*EE2], g_Wtl[4*EE2];    // transposed weights
__device__ float    g_Vt[NSE];                      // fp32 staging for V
__device__ float    g_attn_fb[NHSS];

#define CPA16(saddr, gptr) asm volatile("cp.async.cg.shared.global [%0], [%1], 16;\n" :: "r"(saddr), "l"(gptr))
#define CPCOMMIT() asm volatile("cp.async.commit_group;\n")
#define CPWAIT(n)  asm volatile("cp.async.wait_group %0;\n" :: "n"(n))

__device__ __forceinline__ void pack2(float x, float y, unsigned& h, unsigned& l) {
  __nv_bfloat162 hh = __float22bfloat162_rn(make_float2(x, y));
  float2 f = __bfloat1622float2(hh);
  __nv_bfloat162 ll = __float22bfloat162_rn(make_float2(x - f.x, y - f.y));
  h = *reinterpret_cast<unsigned*>(&hh);
  l = *reinterpret_cast<unsigned*>(&ll);
}

__device__ __forceinline__ void mma4(float* c, const unsigned* a, unsigned b0, unsigned b1) {
  asm volatile(
      "mma.sync.aligned.m16n8k16.row.col.f32.bf16.bf16.f32 "
      "{%0,%1,%2,%3}, {%4,%5,%6,%7}, {%8,%9}, {%0,%1,%2,%3};\n"
      : "+f"(c[0]), "+f"(c[1]), "+f"(c[2]), "+f"(c[3])
      : "r"(a[0]), "r"(a[1]), "r"(a[2]), "r"(a[3]), "r"(b0), "r"(b1));
}

// 3-term split mma over CH k16-chunks from packed planes (pitch in words).
template <int MT, int NT, int PITCH, int CH>
__device__ __forceinline__ void compute_tile2(
    const unsigned* Ah, const unsigned* Al, const unsigned* Bh, const unsigned* Bl,
    int wm0, int wn0, int gr, int q, float (&acc)[MT][NT][4]) {
#pragma unroll
  for (int c = 0; c < CH; c++) {
    unsigned ah[MT][4], al[MT][4];
#pragma unroll
    for (int mt = 0; mt < MT; mt++) {
      int r0 = (wm0 + 16*mt + gr)*PITCH + 8*c + q;
      int r1 = (wm0 + 16*mt + 8 + gr)*PITCH + 8*c + q;
      ah[mt][0]=Ah[r0]; ah[mt][1]=Ah[r1]; ah[mt][2]=Ah[r0+4]; ah[mt][3]=Ah[r1+4];
      al[mt][0]=Al[r0]; al[mt][1]=Al[r1]; al[mt][2]=Al[r0+4]; al[mt][3]=Al[r1+4];
    }
#pragma unroll
    for (int nt = 0; nt < NT; nt++) {
      int rb = (wn0 + 8*nt + gr)*PITCH + 8*c + q;
      unsigned bh0=Bh[rb], bh1=Bh[rb+4], bl0=Bl[rb], bl1=Bl[rb+4];
#pragma unroll
      for (int mt = 0; mt < MT; mt++) {
        mma4(acc[mt][nt], ah[mt], bh0, bh1);
        mma4(acc[mt][nt], ah[mt], bl0, bl1);
        mma4(acc[mt][nt], al[mt], bh0, bh1);
      }
    }
  }
}

// fp32 -> planes, linear pairs (grid-stride)
__global__ void convert_pack(const float* __restrict__ src,
                             unsigned* __restrict__ h, unsigned* __restrict__ l, int npairs) {
  for (int i = blockIdx.x*blockDim.x + threadIdx.x; i < npairs; i += gridDim.x*blockDim.x) {
    float2 v = ((const float2*)src)[i];
    pack2(v.x, v.y, h[i], l[i]);
  }
}

// W[k][n] fp32 -> Wt planes [n][k/2]
__global__ __launch_bounds__(256) void transpose_convert(
    const float* __restrict__ W, unsigned* __restrict__ Th, unsigned* __restrict__ Tl) {
  __shared__ float tile[32][33];
  int bx = blockIdx.x*32, by = blockIdx.y*32;
  int t = threadIdx.x, x = t & 31, y = t >> 5;
#pragma unroll
  for (int i = 0; i < 4; i++)
    tile[y + 8*i][x] = W[(size_t)(by + y + 8*i)*1024 + bx + x];
  __syncthreads();
#pragma unroll
  for (int j = 0; j < 2; j++) {
    int idx = t + 256*j;
    int n = idx >> 4, p = idx & 15;
    unsigned h, l;
    pack2(tile[2*p][n], tile[2*p+1][n], h, l);
    Th[(size_t)(bx + n)*512 + (by >> 1) + p] = h;
    Tl[(size_t)(bx + n)*512 + (by >> 1) + p] = l;
  }
}

// fp32 tile load + inline split (for softmax output P only)
template <int OUTER>
__device__ __forceinline__ void load_tile_f32(const float* __restrict__ g, int ld,
                                              unsigned* sh, unsigned* sl, int tid) {
#pragma unroll
  for (int j = 0; j < OUTER/32; j++) {
    int e = tid + 256*j;
    int m = e >> 3, kq = e & 7;
    float4 v = *(const float4*)(g + (size_t)m*ld + 4*kq);
    unsigned h01, h23, l01, l23;
    pack2(v.x, v.y, h01, l01);
    pack2(v.z, v.w, h23, l23);
    int base = m*20 + 2*kq;
    sh[base]=h01; sh[base+1]=h23; sl[base]=l01; sl[base+1]=l23;
  }
}

__device__ __forceinline__ void proj_issue(
    unsigned sbase, const unsigned* Ah_g, const unsigned* Al_g,
    const unsigned* Bh_g, const unsigned* Bl_g, int m0, int n0, int kt2, int tid) {
#pragma unroll
  for (int j = 0; j < 2; j++) {
    int c = tid + 256*j;
    int m = c >> 2, kc = c & 3;
    unsigned d = sbase + (unsigned)((m*20 + kc*4)*4);
    size_t ga = (size_t)m*512 + kt2 + kc*4;
    CPA16(d + 0u*10240u, Ah_g + (size_t)m0*512 + ga);
    CPA16(d + 1u*10240u, Al_g + (size_t)m0*512 + ga);
    CPA16(d + 2u*10240u, Bh_g + (size_t)n0*512 + ga);
    CPA16(d + 3u*10240u, Bl_g + (size_t)n0*512 + ga);
  }
}

// ---------------------------------------------------------------------------
// Projection GEMM from planes. EPI: 0=write planes, 1=write fp32, 2=write Vt fp32
// CTA 128x128, 2-stage cp.async pipeline, dyn smem 81920B.
// ---------------------------------------------------------------------------
template <int EPI>
__global__ __launch_bounds__(256, 2) void proj_mma(
    const unsigned* __restrict__ Ah_g, const unsigned* __restrict__ Al_g,
    const unsigned* __restrict__ Bh_g, const unsigned* __restrict__ Bl_g,
    const float* __restrict__ bias, float* __restrict__ Cf,
    unsigned* __restrict__ Ch, unsigned* __restrict__ Cl) {
  extern __shared__ unsigned sm[];
  const int tid = threadIdx.x, wid = tid >> 5, lane = tid & 31;
  const int gr = lane >> 2, q = lane & 3;
  const int wm0 = (wid >> 2)*64, wn0 = (wid & 3)*32;
  const int m0 = blockIdx.y*128, n0 = blockIdx.x*128;
  unsigned smu = (unsigned)__cvta_generic_to_shared(sm);
  float acc[4][4][4] = {};
  proj_issue(smu, Ah_g, Al_g, Bh_g, Bl_g, m0, n0, 0, tid);
  CPCOMMIT();
  for (int t = 0; t < 32; t++) {
    if (t + 1 < 32)
      proj_issue(smu + ((t+1)&1)*40960u, Ah_g, Al_g, Bh_g, Bl_g, m0, n0, (t+1)*16, tid);
    CPCOMMIT();
    CPWAIT(1);
    __syncthreads();
    const unsigned* base = sm + (t&1)*10240;
    compute_tile2<4,4,20,2>(base, base+2560, base+5120, base+7680, wm0, wn0, gr, q, acc);
    __syncthreads();
  }
#pragma unroll
  for (int mt = 0; mt < 4; mt++) {
#pragma unroll
    for (int nt = 0; nt < 4; nt++) {
      int row = m0 + wm0 + 16*mt + gr;
      int col = n0 + wn0 + 8*nt + 2*q;
      float b0 = bias[col], b1 = bias[col+1];
      float v0 = acc[mt][nt][0] + b0, v1 = acc[mt][nt][1] + b1;
      float v2 = acc[mt][nt][2] + b0, v3 = acc[mt][nt][3] + b1;
      if (EPI == 0) {
        int w = col >> 1;
        pack2(v0, v1, Ch[(size_t)row*512 + w], Cl[(size_t)row*512 + w]);
        pack2(v2, v3, Ch[(size_t)(row+8)*512 + w], Cl[(size_t)(row+8)*512 + w]);
      } else if (EPI == 1) {
        *(float2*)&Cf[(size_t)row*1024 + col] = make_float2(v0, v1);
        *(float2*)&Cf[(size_t)(row+8)*1024 + col] = make_float2(v2, v3);
      } else {
        int nb = row >> 10, s = row & 1023;
        int h = col >> 6, d = col & 63;
        float* p = Cf + (((size_t)(nb*16 + h))*64 + d)*1024 + s;
        p[0] = v0; p[1024] = v1; p[8] = v2; p[1024 + 8] = v3;
      }
    }
  }
}

// ---------------------------------------------------------------------------
// QK^T from planes: single smem load (full K=64), dyn smem 73728B.
// ---------------------------------------------------------------------------
__global__ __launch_bounds__(256, 2) void qk_mma(
    const int* __restrict__ mask, float* __restrict__ attn) {
  extern __shared__ unsigned sm[];
  const int tid = threadIdx.x, wid = tid >> 5, lane = tid & 31;
  const int gr = lane >> 2, q = lane & 3;
  const int wm0 = (wid >> 2)*64, wn0 = (wid & 3)*32;
  const int t0 = blockIdx.x*128, m0 = blockIdx.y*128;
  const int nh = blockIdx.z, nb = nh >> 4, h = nh & 15;
  unsigned smu = (unsigned)__cvta_generic_to_shared(sm);
  const size_t qoff = (size_t)(nb*1024 + m0)*512 + h*32;
  const size_t koff = (size_t)(nb*1024 + t0)*512 + h*32;
#pragma unroll
  for (int j = 0; j < 4; j++) {
    int c = tid + 256*j;
    int m = c >> 3, kc = c & 7;
    unsigned d = smu + (unsigned)((m*36 + kc*4)*4);
    size_t ga = (size_t)m*512 + kc*4;
    CPA16(d + 0u*18432u, g_Qh + qoff + ga);
    CPA16(d + 1u*18432u, g_Ql + qoff + ga);
    CPA16(d + 2u*18432u, g_Kh + koff + ga);
    CPA16(d + 3u*18432u, g_Kl + koff + ga);
  }
  CPCOMMIT();
  CPWAIT(0);
  __syncthreads();
  float acc[4][4][4] = {};
  compute_tile2<4,4,36,4>(sm, sm+4608, sm+9216, sm+13824, wm0, wn0, gr, q, acc);
#pragma unroll
  for (int mt = 0; mt < 4; mt++) {
#pragma unroll
    for (int nt = 0; nt < 4; nt++) {
      int row = m0 + wm0 + 16*mt + gr;
      int t = t0 + wn0 + 8*nt + 2*q;
      int2 mA = *(const int2*)&mask[(size_t)(nb*1024 + row)*1024 + t];
      int2 mB = *(const int2*)&mask[(size_t)(nb*1024 + row + 8)*1024 + t];
      float2 v0, v1;
      v0.x = mA.x ? -1e9f : acc[mt][nt][0]*0.125f;
      v0.y = mA.y ? -1e9f : acc[mt][nt][1]*0.125f;
      v1.x = mB.x ? -1e9f : acc[mt][nt][2]*0.125f;
      v1.y = mB.y ? -1e9f : acc[mt][nt][3]*0.125f;
      *(float2*)&attn[((size_t)nh*1024 + row)*1024 + t] = v0;
      *(float2*)&attn[((size_t)nh*1024 + row + 8)*1024 + t] = v1;
    }
  }
}

// ---------------------------------------------------------------------------
// In-place row softmax, rows of 1024.
// ---------------------------------------------------------------------------
__global__ __launch_bounds__(256) void softmax_kernel(float* __restrict__ attn) {
  __shared__ float red[8];
  const int tid = threadIdx.x;
  size_t rowIdx = (size_t)blockIdx.y*1024 + blockIdx.x;
  float* row = attn + rowIdx*1024;
  float4 v = ((float4*)row)[tid];
  float m = fmaxf(fmaxf(v.x, v.y), fmaxf(v.z, v.w));
#pragma unroll
  for (int o = 16; o > 0; o >>= 1) m = fmaxf(m, __shfl_xor_sync(0xffffffffu, m, o));
  if ((tid & 31) == 0) red[tid >> 5] = m;
  __syncthreads();
  m = fmaxf(fmaxf(fmaxf(red[0], red[1]), fmaxf(red[2], red[3])),
            fmaxf(fmaxf(red[4], red[5]), fmaxf(red[6], red[7])));
  float4 e;
  e.x = __expf(v.x - m); e.y = __expf(v.y - m);
  e.z = __expf(v.z - m); e.w = __expf(v.w - m);
  float s = (e.x + e.y) + (e.z + e.w);
#pragma unroll
  for (int o = 16; o > 0; o >>= 1) s += __shfl_xor_sync(0xffffffffu, s, o);
  __syncthreads();
  if ((tid & 31) == 0) red[tid >> 5] = s;
  __syncthreads();
  s = ((red[0]+red[1]) + (red[2]+red[3])) + ((red[4]+red[5]) + (red[6]+red[7]));
  float inv = 1.0f / s;
  e.x *= inv; e.y *= inv; e.z *= inv; e.w *= inv;
  ((float4*)row)[tid] = e;
}

// ---------------------------------------------------------------------------
// PV: A = softmax P (fp32, inline split), B = Vt planes. Writes O planes.
// ---------------------------------------------------------------------------
__global__ __launch_bounds__(256, 2) void pv_mma(const float* __restrict__ attn) {
  __shared__ unsigned Ah[2560], Al[2560], Bh[1280], Bl[1280];
  const int tid = threadIdx.x, wid = tid >> 5, lane = tid & 31;
  const int gr = lane >> 2, q = lane & 3;
  const int wm0 = (wid >> 2)*64, wn0 = (wid & 3)*16;
  const int m0 = blockIdx.x*128;
  const int nh = blockIdx.y, nb = nh >> 4, h = nh & 15;
  const float* P = attn + (size_t)nh*1024*1024 + (size_t)m0*1024;
  float acc[4][2][4] = {};
  for (int kt = 0; kt < 1024; kt += 32) {
    load_tile_f32<128>(P + kt, 1024, Ah, Al, tid);
    {
      int m = tid >> 2, kc = tid & 3;
      if (m < 64) {
        size_t src = (size_t)(nh*64 + m)*512 + (kt >> 1) + kc*4;
        *(uint4*)&Bh[m*20 + kc*4] = *(const uint4*)&g_Vth[src];
        *(uint4*)&Bl[m*20 + kc*4] = *(const uint4*)&g_Vtl[src];
      }
    }
    __syncthreads();
    compute_tile2<4,2,20,2>(Ah, Al, Bh, Bl, wm0, wn0, gr, q, acc);
    __syncthreads();
  }
#pragma unroll
  for (int mt = 0; mt < 4; mt++) {
#pragma unroll
    for (int nt = 0; nt < 2; nt++) {
      int s = m0 + wm0 + 16*mt + gr;
      int col = h*64 + wn0 + 8*nt + 2*q;
      int w = col >> 1;
      size_t r0 = (size_t)(nb*1024 + s)*512 + w;
      size_t r1 = (size_t)(nb*1024 + s + 8)*512 + w;
      pack2(acc[mt][nt][0], acc[mt][nt][1], g_Oh[r0], g_Ol[r0]);
      pack2(acc[mt][nt][2], acc[mt][nt][3], g_Oh[r1], g_Ol[r1]);
    }
  }
}

// ---------------------------------------------------------------------------
extern "C" void kernel_launch(void* const* d_in, const int* in_sizes, int n_in,
                              void* d_out, int out_size) {
  const float* q  = (const float*)d_in[0];
  const float* k  = (const float*)d_in[1];
  const float* v  = (const float*)d_in[2];
  const int*   mask = (const int*)d_in[3];
  const float* wq = (const float*)d_in[4];
  const float* bq = (const float*)d_in[5];
  const float* wk = (const float*)d_in[6];
  const float* bk = (const float*)d_in[7];
  const float* wv = (const float*)d_in[8];
  const float* bv = (const float*)d_in[9];
  const float* wo = (const float*)d_in[10];
  const float* bo = (const float*)d_in[11];
  float* out = (float*)d_out;

  static bool attr_done = false;
  if (!attr_done) {
    cudaFuncSetAttribute(proj_mma<0>, cudaFuncAttributeMaxDynamicSharedMemorySize, 81920);
    cudaFuncSetAttribute(proj_mma<1>, cudaFuncAttributeMaxDynamicSharedMemorySize, 81920);
    cudaFuncSetAttribute(proj_mma<2>, cudaFuncAttributeMaxDynamicSharedMemorySize, 81920);
    cudaFuncSetAttribute(qk_mma, cudaFuncAttributeMaxDynamicSharedMemorySize, 73728);
    attr_done = true;
  }

  unsigned *Inh, *Inl, *Qh, *Ql, *Kh, *Kl, *Vth, *Vtl, *Oh, *Ol, *Wth, *Wtl;
  float *Vtp, *attn;
  cudaGetSymbolAddress((void**)&Inh, g_Inh);  cudaGetSymbolAddress((void**)&Inl, g_Inl);
  cudaGetSymbolAddress((void**)&Qh, g_Qh);    cudaGetSymbolAddress((void**)&Ql, g_Ql);
  cudaGetSymbolAddress((void**)&Kh, g_Kh);    cudaGetSymbolAddress((void**)&Kl, g_Kl);
  cudaGetSymbolAddress((void**)&Vth, g_Vth);  cudaGetSymbolAddress((void**)&Vtl, g_Vtl);
  cudaGetSymbolAddress((void**)&Oh, g_Oh);    cudaGetSymbolAddress((void**)&Ol, g_Ol);
  cudaGetSymbolAddress((void**)&Wth, g_Wth);  cudaGetSymbolAddress((void**)&Wtl, g_Wtl);
  cudaGetSymbolAddress((void**)&Vtp, g_Vt);
  if ((long long)out_size >= (long long)NSE + (long long)NHSS) {
    attn = out + NSE;
  } else {
    cudaGetSymbolAddress((void**)&attn, g_attn_fb);
  }

  dim3 tg(32, 32);
  transpose_convert<<<tg, 256>>>(wq, Wth + 0*EE2, Wtl + 0*EE2);
  transpose_convert<<<tg, 256>>>(wk, Wth + 1*EE2, Wtl + 1*EE2);
  transpose_convert<<<tg, 256>>>(wv, Wth + 2*EE2, Wtl + 2*EE2);
  transpose_convert<<<tg, 256>>>(wo, Wth + 3*EE2, Wtl + 3*EE2);

  dim3 gp(8, 64);
  convert_pack<<<2048, 256>>>(q, Inh, Inl, NSE2);
  proj_mma<0><<<gp, 256, 81920>>>(Inh, Inl, Wth + 0*EE2, Wtl + 0*EE2, bq, nullptr, Qh, Ql);
  convert_pack<<<2048, 256>>>(k, Inh, Inl, NSE2);
  proj_mma<0><<<gp, 256, 81920>>>(Inh, Inl, Wth + 1*EE2, Wtl + 1*EE2, bk, nullptr, Kh, Kl);
  convert_pack<<<2048, 256>>>(v, Inh, Inl, NSE2);
  proj_mma<2><<<gp, 256, 81920>>>(Inh, Inl, Wth + 2*EE2, Wtl + 2*EE2, bv, Vtp, nullptr, nullptr);
  convert_pack<<<2048, 256>>>(Vtp, Vth, Vtl, NSE2);

  qk_mma<<<dim3(8, 8, 128), 256, 73728>>>(mask, attn);
  softmax_kernel<<<dim3(1024, 128), 256>>>(attn);
  pv_mma<<<dim3(8, 128), 256>>>(attn);
  proj_mma<1><<<gp, 256, 81920>>>(Oh, Ol, Wth + 3*EE2, Wtl + 3*EE2, bo, out, nullptr, nullptr);
}